// round 3
// baseline (speedup 1.0000x reference)
#include <cuda_runtime.h>
#include <cstdint>

// EvalBspPrimeTF: derivative of Bernstein basis of order 16 at 4M points.
//   out[0]  = -16 * (1-y)^15
//   out[m]  =  16 * ( C(15,m-1) y^(m-1) (1-y)^(16-m) - C(15,m) y^m (1-y)^(15-m) ),  1<=m<=15
//   out[16] =  16 * y^15
// Reference NaN->0: at y==0, out[0]=out[1]=0; at y==1, out[15]=out[16]=0.
//
// R3: persistent CTAs, double-buffered smem + pipelined TMA bulk stores.
// Compute of tile i overlaps the async bulk store of tile i-1, keeping the
// DRAM write stream continuous instead of bursty.

#define TPB   256
#define NCOL  17
#define TILE_WORDS (TPB * NCOL)          // 4352 floats
#define TILE_BYTES (TILE_WORDS * 4)      // 17408 B, multiple of 16
#define NBUF  2
#define GRID_CTAS 888                    // 148 SMs * 6 resident CTAs

__global__ __launch_bounds__(TPB)
void evalbspprime_kernel(const float* __restrict__ x,
                         float* __restrict__ out,
                         int n)
{
    __shared__ __align__(128) float s[NBUF][TILE_WORDS];   // 34816 B

    const float C15[16] = {
        1.f, 15.f, 105.f, 455.f, 1365.f, 3003.f, 5005.f, 6435.f,
        6435.f, 5005.f, 3003.f, 1365.f, 455.f, 105.f, 15.f, 1.f
    };

    const int tid    = threadIdx.x;
    const int ntiles = (n + TPB - 1) / TPB;

    int it = 0;
    for (int t = blockIdx.x; t < ntiles; t += gridDim.x, ++it) {
        const int base = t * TPB;
        const int idx  = base + tid;
        const int buf  = it & 1;

        // ---- compute (registers only; overlaps in-flight TMA stores) ----
        float y = (idx < n) ? x[idx] : 0.5f;
        float q = 1.0f - y;

        float yp[16], qp[16];
        yp[0] = 1.0f; qp[0] = 1.0f;
#pragma unroll
        for (int k = 1; k < 16; ++k) {
            yp[k] = yp[k - 1] * y;
            qp[k] = qp[k - 1] * q;
        }

        float o[NCOL];
        o[0]  = -16.0f * qp[15];
#pragma unroll
        for (int m = 1; m < 16; ++m) {
            o[m] = 16.0f * (C15[m - 1] * yp[m - 1] * qp[16 - m]
                          - C15[m]     * yp[m]     * qp[15 - m]);
        }
        o[16] = 16.0f * yp[15];

        if (y == 0.0f) { o[0]  = 0.0f; o[1]  = 0.0f; }
        if (y == 1.0f) { o[15] = 0.0f; o[16] = 0.0f; }

        // ---- reclaim this buffer: the store issued 2 iterations ago used it.
        // Commits are in-order, so read<=1 outstanding guarantees it drained.
        if (tid == 0)
            asm volatile("cp.async.bulk.wait_group.read 1;" ::: "memory");
        __syncthreads();

        // ---- stage: stride-17 words per thread, 17 coprime 32 banks -> conflict-free
#pragma unroll
        for (int m = 0; m < NCOL; ++m)
            s[buf][tid * NCOL + m] = o[m];

        __syncthreads();

        if (base + TPB <= n) {
            if (tid == 0) {
                asm volatile("fence.proxy.async.shared::cta;" ::: "memory");
                uint32_t saddr = (uint32_t)__cvta_generic_to_shared(&s[buf][0]);
                const float* g = out + (long long)base * NCOL;
                asm volatile(
                    "cp.async.bulk.global.shared::cta.bulk_group [%0], [%1], %2;"
                    :: "l"(g), "r"(saddr), "n"(TILE_BYTES) : "memory");
                asm volatile("cp.async.bulk.commit_group;" ::: "memory");
            }
        } else {
            // tail tile (absent for n = 4,000,000): coalesced scalar fallback
            const long long obase = (long long)base * NCOL;
            const int rem = (n - base) * NCOL;
            for (int i = tid; i < rem; i += TPB)
                out[obase + i] = s[buf][i];
            __syncthreads();
        }
    }

    // drain all outstanding bulk stores before CTA exit (smem dealloc safety)
    if (tid == 0)
        asm volatile("cp.async.bulk.wait_group.read 0;" ::: "memory");
}

extern "C" void kernel_launch(void* const* d_in, const int* in_sizes, int n_in,
                              void* d_out, int out_size)
{
    const float* x = (const float*)d_in[0];
    float* out = (float*)d_out;
    const int n = in_sizes[0];          // 4,000,000 points
    const int ntiles = (n + TPB - 1) / TPB;
    const int blocks = ntiles < GRID_CTAS ? ntiles : GRID_CTAS;
    evalbspprime_kernel<<<blocks, TPB>>>(x, out, n);
}

// round 4
// speedup vs baseline: 1.1245x; 1.1245x over previous
#include <cuda_runtime.h>
#include <cstdint>

// EvalBspPrimeTF: derivative of Bernstein basis, order 16, 4M points -> [4M,17] f32.
// Telescoping form: U_m = 16*C(15,m)*y^m*(1-y)^(15-m), m=0..15
//   out[0] = -U_0;  out[m] = U_{m-1} - U_m (1<=m<=15);  out[16] = U_15
// Reference NaN->0: at y==0, out[0]=out[1]=0; at y==1, out[15]=out[16]=0.
//
// R4: non-persistent blocks, 2 tiles per CTA, double-buffered smem, two
// pipelined TMA bulk stores per CTA with a single drain at the end.

#define TPB   256
#define NCOL  17
#define TILE_WORDS (TPB * NCOL)          // 4352 floats
#define TILE_BYTES (TILE_WORDS * 4)      // 17408 B
#define TILES_PER_CTA 2

__device__ __forceinline__ void compute_point(float y, float* __restrict__ o)
{
    // 16*C(15,m)
    const float K[16] = {
        16.f, 240.f, 1680.f, 7280.f, 21840.f, 48048.f, 80080.f, 102960.f,
        102960.f, 80080.f, 48048.f, 21840.f, 7280.f, 1680.f, 240.f, 16.f
    };
    float q = 1.0f - y;

    float yp[16], qp[16];
    yp[0] = 1.0f; qp[0] = 1.0f;
#pragma unroll
    for (int k = 1; k < 16; ++k) {
        yp[k] = yp[k - 1] * y;
        qp[k] = qp[k - 1] * q;
    }

    float U[16];
#pragma unroll
    for (int m = 0; m < 16; ++m)
        U[m] = K[m] * yp[m] * qp[15 - m];

    o[0] = -U[0];
#pragma unroll
    for (int m = 1; m < 16; ++m)
        o[m] = U[m - 1] - U[m];
    o[16] = U[15];

    if (y == 0.0f) { o[0]  = 0.0f; o[1]  = 0.0f; }
    if (y == 1.0f) { o[15] = 0.0f; o[16] = 0.0f; }
}

__global__ __launch_bounds__(TPB)
void evalbspprime_kernel(const float* __restrict__ x,
                         float* __restrict__ out,
                         int n)
{
    __shared__ __align__(128) float s[TILES_PER_CTA][TILE_WORDS];  // 34816 B

    const int tid    = threadIdx.x;
    const int ntiles = (n + TPB - 1) / TPB;

#pragma unroll
    for (int sub = 0; sub < TILES_PER_CTA; ++sub) {
        const int t = blockIdx.x * TILES_PER_CTA + sub;
        if (t >= ntiles) break;
        const int base = t * TPB;
        const int idx  = base + tid;

        float y = (idx < n) ? x[idx] : 0.5f;
        float o[NCOL];
        compute_point(y, o);

        // stride-17 words per thread: 17 coprime to 32 banks -> conflict-free
#pragma unroll
        for (int m = 0; m < NCOL; ++m)
            s[sub][tid * NCOL + m] = o[m];

        __syncthreads();

        if (base + TPB <= n) {
            if (tid == 0) {
                asm volatile("fence.proxy.async.shared::cta;" ::: "memory");
                uint32_t saddr = (uint32_t)__cvta_generic_to_shared(&s[sub][0]);
                const float* g = out + (long long)base * NCOL;
                asm volatile(
                    "cp.async.bulk.global.shared::cta.bulk_group [%0], [%1], %2;"
                    :: "l"(g), "r"(saddr), "n"(TILE_BYTES) : "memory");
                asm volatile("cp.async.bulk.commit_group;" ::: "memory");
            }
            // no wait here: next sub uses the other buffer; store drains under
            // the next tile's compute.
        } else {
            const long long obase = (long long)base * NCOL;
            const int rem = (n - base) * NCOL;
            for (int i = tid; i < rem; i += TPB)
                out[obase + i] = s[sub][i];
            __syncthreads();
        }
    }

    // single drain before CTA exit (smem dealloc safety)
    if (tid == 0)
        asm volatile("cp.async.bulk.wait_group.read 0;" ::: "memory");
}

extern "C" void kernel_launch(void* const* d_in, const int* in_sizes, int n_in,
                              void* d_out, int out_size)
{
    const float* x = (const float*)d_in[0];
    float* out = (float*)d_out;
    const int n = in_sizes[0];          // 4,000,000
    const int ntiles = (n + TPB - 1) / TPB;                    // 15625
    const int blocks = (ntiles + TILES_PER_CTA - 1) / TILES_PER_CTA;  // 7813
    evalbspprime_kernel<<<blocks, TPB>>>(x, out, n);
}

// round 5
// speedup vs baseline: 1.1491x; 1.0219x over previous
#include <cuda_runtime.h>
#include <cstdint>

// EvalBspPrimeTF: derivative of Bernstein basis, order 16, 4M points -> [4M,17] f32.
// Telescoping form: U_m = 16*C(15,m)*y^m*(1-y)^(15-m), m=0..15
//   out[0] = -U_0;  out[m] = U_{m-1} - U_m (1<=m<=15);  out[16] = U_15
// Reference NaN->0: at y==0, out[0]=out[1]=0; at y==1, out[15]=out[16]=0.
//
// R5: small tiles — TPB=128, one 8704B TMA bulk store per CTA, 31250 CTAs.
// Many small resident CTAs (8.7KB smem each) hide the per-CTA tail drain and
// give the memory system many independent write bursts.

#define TPB   128
#define NCOL  17
#define TILE_WORDS (TPB * NCOL)          // 2176 floats
#define TILE_BYTES (TILE_WORDS * 4)      // 8704 B, multiple of 16

__device__ __forceinline__ void compute_point(float y, float* __restrict__ o)
{
    // 16*C(15,m)
    const float K[16] = {
        16.f, 240.f, 1680.f, 7280.f, 21840.f, 48048.f, 80080.f, 102960.f,
        102960.f, 80080.f, 48048.f, 21840.f, 7280.f, 1680.f, 240.f, 16.f
    };
    float q = 1.0f - y;

    float yp[16], qp[16];
    yp[0] = 1.0f; qp[0] = 1.0f;
#pragma unroll
    for (int k = 1; k < 16; ++k) {
        yp[k] = yp[k - 1] * y;
        qp[k] = qp[k - 1] * q;
    }

    float U[16];
#pragma unroll
    for (int m = 0; m < 16; ++m)
        U[m] = K[m] * yp[m] * qp[15 - m];

    o[0] = -U[0];
#pragma unroll
    for (int m = 1; m < 16; ++m)
        o[m] = U[m - 1] - U[m];
    o[16] = U[15];

    if (y == 0.0f) { o[0]  = 0.0f; o[1]  = 0.0f; }
    if (y == 1.0f) { o[15] = 0.0f; o[16] = 0.0f; }
}

__global__ __launch_bounds__(TPB)
void evalbspprime_kernel(const float* __restrict__ x,
                         float* __restrict__ out,
                         int n)
{
    __shared__ __align__(128) float s[TILE_WORDS];   // 8704 B

    const int tid  = threadIdx.x;
    const int base = blockIdx.x * TPB;
    const int idx  = base + tid;

    float y = (idx < n) ? x[idx] : 0.5f;
    float o[NCOL];
    compute_point(y, o);

    // stride-17 words per thread: 17 coprime to 32 banks -> conflict-free
#pragma unroll
    for (int m = 0; m < NCOL; ++m)
        s[tid * NCOL + m] = o[m];

    __syncthreads();

    if (base + TPB <= n) {
        if (tid == 0) {
            asm volatile("fence.proxy.async.shared::cta;" ::: "memory");
            uint32_t saddr = (uint32_t)__cvta_generic_to_shared(s);
            const float* g = out + (long long)base * NCOL;
            asm volatile(
                "cp.async.bulk.global.shared::cta.bulk_group [%0], [%1], %2;"
                :: "l"(g), "r"(saddr), "n"(TILE_BYTES) : "memory");
            asm volatile("cp.async.bulk.commit_group;" ::: "memory");
            // drain before CTA exit (smem dealloc safety)
            asm volatile("cp.async.bulk.wait_group.read 0;" ::: "memory");
        }
    } else {
        // tail (absent for n = 4,000,000): coalesced scalar fallback
        const long long obase = (long long)base * NCOL;
        const int rem = (n - base) * NCOL;
        for (int i = tid; i < rem; i += TPB)
            out[obase + i] = s[i];
    }
}

extern "C" void kernel_launch(void* const* d_in, const int* in_sizes, int n_in,
                              void* d_out, int out_size)
{
    const float* x = (const float*)d_in[0];
    float* out = (float*)d_out;
    const int n = in_sizes[0];          // 4,000,000
    const int blocks = (n + TPB - 1) / TPB;   // 31250
    evalbspprime_kernel<<<blocks, TPB>>>(x, out, n);
}